// round 9
// baseline (speedup 1.0000x reference)
#include <cuda_runtime.h>
#include <cuda_bf16.h>
#include <cstdint>

// IoU kernel: elementwise over N boxes, A=5 anchors.
// Inputs (metadata order):
//   d_in[0]: cell_nos  int32  [N,2]
//   d_in[1]: output    float  [N,5,5]
//   d_in[2]: target    float  [N,5]
// Output: float [N,5]
//
// Persistent CTAs with a 2-stage double-buffered TMA pipeline:
//   - each CTA owns tiles {bid, bid+G, ...}; prologue issues loads for tiles
//     0 and 1 (stages 0/1); steady state: wait mbar(s) -> compute -> store
//     res(s) via bulk_group -> immediately issue loads for tile k+2 into
//     stage s. Store-buffer reuse guarded by cp.async.bulk.wait_group 1.
//   - all bulk traffic on the TMA path (no LSU/L1tex involvement).

#define YI 20.0f
#define BPB 256           // boxes per tile == threads per block
#define A 5               // anchors

#define OUT_F (BPB * 25)
#define TGT_F (BPB * 5)
#define CEL_I (BPB * 2)
#define OUT_BYTES (OUT_F * 4)                      // 25600
#define TGT_BYTES (TGT_F * 4)                      //  5120
#define CEL_BYTES (CEL_I * 4)                      //  2048
#define STAGE_BYTES (OUT_BYTES + TGT_BYTES + CEL_BYTES)  // 32768
#define RES_BYTES  TGT_BYTES                       //  5120
#define SMEM_TOTAL (2 * STAGE_BYTES + 2 * RES_BYTES)     // 75776

#define GRID_CTAS 456     // 3 CTAs/SM x 152 SMs (GB300)

extern __shared__ char dsm[];

__device__ __forceinline__ void mbar_wait(uint32_t mbar_a, uint32_t parity) {
    uint32_t done;
    asm volatile(
        "{\n\t"
        ".reg .pred p;\n\t"
        "mbarrier.try_wait.parity.acquire.cta.shared::cta.b64 p, [%1], %2;\n\t"
        "selp.b32 %0, 1, 0, p;\n\t"
        "}"
        : "=r"(done) : "r"(mbar_a), "r"(parity) : "memory");
    if (!done) {
        asm volatile(
            "{\n\t"
            ".reg .pred P1;\n\t"
            "WAIT_LOOP_%=:\n\t"
            "mbarrier.try_wait.parity.acquire.cta.shared::cta.b64 P1, [%0], %1, 0x989680;\n\t"
            "@P1 bra.uni WAIT_DONE_%=;\n\t"
            "bra.uni WAIT_LOOP_%=;\n\t"
            "WAIT_DONE_%=:\n\t"
            "}"
            :: "r"(mbar_a), "r"(parity) : "memory");
    }
}

__global__ __launch_bounds__(BPB) void iou_kernel(
    const int* __restrict__ cell_nos,
    const float* __restrict__ output,
    const float* __restrict__ target,
    float* __restrict__ res,
    int n)
{
    __shared__ alignas(8) unsigned long long mbar[2];

    const int tid = threadIdx.x;
    const int G   = gridDim.x;
    const int bid = blockIdx.x;
    const int ntiles = n / BPB;

    // Stage pointers in dynamic smem.
    float* s_out[2];
    float* s_tgt[2];
    int*   s_cell[2];
    float* s_res[2];
    #pragma unroll
    for (int s = 0; s < 2; s++) {
        char* sb = dsm + s * STAGE_BYTES;
        s_out[s]  = reinterpret_cast<float*>(sb);
        s_tgt[s]  = reinterpret_cast<float*>(sb + OUT_BYTES);
        s_cell[s] = reinterpret_cast<int*>(sb + OUT_BYTES + TGT_BYTES);
        s_res[s]  = reinterpret_cast<float*>(dsm + 2 * STAGE_BYTES + s * RES_BYTES);
    }
    uint32_t mbar_a[2];
    mbar_a[0] = (uint32_t)__cvta_generic_to_shared(&mbar[0]);
    mbar_a[1] = (uint32_t)__cvta_generic_to_shared(&mbar[1]);
    uint32_t so_a[2], st_a[2], sc_a[2], sr_a[2];
    #pragma unroll
    for (int s = 0; s < 2; s++) {
        so_a[s] = (uint32_t)__cvta_generic_to_shared(s_out[s]);
        st_a[s] = (uint32_t)__cvta_generic_to_shared(s_tgt[s]);
        sc_a[s] = (uint32_t)__cvta_generic_to_shared(s_cell[s]);
        sr_a[s] = (uint32_t)__cvta_generic_to_shared(s_res[s]);
    }

    if (tid == 0) {
        asm volatile("mbarrier.init.shared::cta.b64 [%0], %1;"
                     :: "r"(mbar_a[0]), "r"(1) : "memory");
        asm volatile("mbarrier.init.shared::cta.b64 [%0], %1;"
                     :: "r"(mbar_a[1]), "r"(1) : "memory");
        asm volatile("fence.proxy.async.shared::cta;" ::: "memory");
    }
    __syncthreads();

    // Tiles owned by this CTA: bid, bid+G, ...
    const int my_nt = (ntiles > bid) ? ((ntiles - 1 - bid) / G + 1) : 0;

    // t0-only: issue the three bulk loads for owned-tile index k into stage s.
    auto issue = [&](int k, int s) {
        const size_t tbase = ((size_t)bid + (size_t)k * G) * BPB;
        asm volatile("mbarrier.arrive.expect_tx.shared::cta.b64 _, [%0], %1;"
                     :: "r"(mbar_a[s]), "r"((uint32_t)STAGE_BYTES) : "memory");
        asm volatile("cp.async.bulk.shared::cta.global.mbarrier::complete_tx::bytes "
                     "[%0], [%1], %2, [%3];"
                     :: "r"(so_a[s]), "l"(output + tbase * 25),
                        "r"((uint32_t)OUT_BYTES), "r"(mbar_a[s]) : "memory");
        asm volatile("cp.async.bulk.shared::cta.global.mbarrier::complete_tx::bytes "
                     "[%0], [%1], %2, [%3];"
                     :: "r"(st_a[s]), "l"(target + tbase * 5),
                        "r"((uint32_t)TGT_BYTES), "r"(mbar_a[s]) : "memory");
        asm volatile("cp.async.bulk.shared::cta.global.mbarrier::complete_tx::bytes "
                     "[%0], [%1], %2, [%3];"
                     :: "r"(sc_a[s]), "l"(cell_nos + tbase * 2),
                        "r"((uint32_t)CEL_BYTES), "r"(mbar_a[s]) : "memory");
    };

    if (tid == 0) {
        if (my_nt > 0) issue(0, 0);
        if (my_nt > 1) issue(1, 1);
    }

    uint32_t ph[2] = {0u, 0u};

    for (int k = 0; k < my_nt; k++) {
        const int s = k & 1;

        // Wait for stage s data (tile k).
        mbar_wait(mbar_a[s], ph[s]);
        ph[s] ^= 1u;

        // Before overwriting s_res[s], ensure the bulk store of tile k-2
        // (same stage) has completed. Groups committed so far: k-2, k-1 at
        // most outstanding -> wait_group 1 guarantees k-2 is done.
        if (tid == 0 && k >= 2) {
            asm volatile("cp.async.bulk.wait_group 1;" ::: "memory");
        }
        __syncthreads();

        // ---- compute tile k from stage s ----
        {
            const float ci = (float)s_cell[s][2 * tid]     * YI + YI * 0.5f;
            const float cj = (float)s_cell[s][2 * tid + 1] * YI + YI * 0.5f;

            const float* t = &s_tgt[s][5 * tid];
            const float g_h = t[3] * YI, g_w = t[4] * YI;
            const float gxc = ci + t[1] * YI;
            const float gyc = cj + t[2] * YI;
            const float gx1 = gyc - g_w * 0.5f;
            const float gy1 = gxc - g_h * 0.5f;
            const float gx2 = gyc + g_w * 0.5f;
            const float gy2 = gxc + g_h * 0.5f;
            const float area_g = (gx2 - gx1) * (gy2 - gy1);

            #pragma unroll
            for (int a = 0; a < A; a++) {
                const float* o = &s_out[s][25 * tid + 5 * a];
                const float p_h = o[3] * YI, p_w = o[4] * YI;
                const float pxc = ci + o[1] * YI;
                const float pyc = cj + o[2] * YI;
                const float px1 = pyc - p_w * 0.5f;
                const float py1 = pxc - p_h * 0.5f;
                const float px2 = pyc + p_w * 0.5f;
                const float py2 = pxc + p_h * 0.5f;
                const float area_p = (px2 - px1) * (py2 - py1);

                const float lx = fmaxf(px1, gx1);
                const float ly = fmaxf(py1, gy1);
                const float rx = fminf(px2, gx2);
                const float ry = fminf(py2, gy2);
                const float iw = fmaxf(rx - lx, 0.0f);
                const float ih = fmaxf(ry - ly, 0.0f);
                const float inter = iw * ih;
                const float uni = area_p + area_g - inter;
                s_res[s][5 * tid + a] = __fdividef(inter, uni);
            }
        }
        __syncthreads();   // results complete; stage s inputs fully consumed

        if (tid == 0) {
            // Drain results for tile k.
            const size_t tbase = ((size_t)bid + (size_t)k * G) * BPB;
            asm volatile("fence.proxy.async.shared::cta;" ::: "memory");
            asm volatile("cp.async.bulk.global.shared::cta.bulk_group [%0], [%1], %2;"
                         :: "l"(res + tbase * 5), "r"(sr_a[s]),
                            "r"((uint32_t)RES_BYTES) : "memory");
            asm volatile("cp.async.bulk.commit_group;" ::: "memory");
            // Prefetch tile k+2 into stage s (inputs free; res[s] guarded by
            // the wait_group at iteration k+2).
            if (k + 2 < my_nt) issue(k + 2, s);
        }
    }

    // Ensure all bulk stores complete before exit.
    if (tid == 0) {
        asm volatile("cp.async.bulk.wait_group 0;" ::: "memory");
    }

    // Tail boxes (n % BPB != 0): direct scalar path (never taken at bench
    // shape N=4,000,000 = 15625*256). Handled by the last CTA.
    const int rem_base = ntiles * BPB;
    if (bid == G - 1 && rem_base + tid < n) {
        const int box = rem_base + tid;
        const float ci = (float)cell_nos[2 * box]     * YI + YI * 0.5f;
        const float cj = (float)cell_nos[2 * box + 1] * YI + YI * 0.5f;
        const float* t = target + (size_t)box * 5;
        const float g_h = t[3] * YI, g_w = t[4] * YI;
        const float gxc = ci + t[1] * YI;
        const float gyc = cj + t[2] * YI;
        const float gx1 = gyc - g_w * 0.5f;
        const float gy1 = gxc - g_h * 0.5f;
        const float gx2 = gyc + g_w * 0.5f;
        const float gy2 = gxc + g_h * 0.5f;
        const float area_g = (gx2 - gx1) * (gy2 - gy1);
        #pragma unroll
        for (int a = 0; a < A; a++) {
            const float* o = output + (size_t)box * 25 + 5 * a;
            const float p_h = o[3] * YI, p_w = o[4] * YI;
            const float pxc = ci + o[1] * YI;
            const float pyc = cj + o[2] * YI;
            const float px1 = pyc - p_w * 0.5f;
            const float py1 = pxc - p_h * 0.5f;
            const float px2 = pyc + p_w * 0.5f;
            const float py2 = pxc + p_h * 0.5f;
            const float area_p = (px2 - px1) * (py2 - py1);
            const float lx = fmaxf(px1, gx1);
            const float ly = fmaxf(py1, gy1);
            const float rx = fminf(px2, gx2);
            const float ry = fminf(py2, gy2);
            const float iw = fmaxf(rx - lx, 0.0f);
            const float ih = fmaxf(ry - ly, 0.0f);
            const float inter = iw * ih;
            res[(size_t)box * 5 + a] = __fdividef(inter, area_p + area_g - inter);
        }
    }
}

extern "C" void kernel_launch(void* const* d_in, const int* in_sizes, int n_in,
                              void* d_out, int out_size) {
    const int*   cell_nos = (const int*)d_in[0];
    const float* output   = (const float*)d_in[1];
    const float* target   = (const float*)d_in[2];
    float*       res      = (float*)d_out;

    const int n = in_sizes[0] / 2;  // cell_nos is [N,2]
    const int ntiles = n / BPB;
    int grid = GRID_CTAS;
    if (grid > ntiles) grid = (ntiles > 0) ? ntiles : 1;

    cudaFuncSetAttribute(iou_kernel,
                         cudaFuncAttributeMaxDynamicSharedMemorySize, SMEM_TOTAL);
    iou_kernel<<<grid, BPB, SMEM_TOTAL>>>(cell_nos, output, target, res, n);
}

// round 12
// speedup vs baseline: 1.4662x; 1.4662x over previous
#include <cuda_runtime.h>
#include <cuda_bf16.h>
#include <cstdint>

// IoU kernel: elementwise over N boxes, A=5 anchors.
// Inputs (metadata order):
//   d_in[0]: cell_nos  int32  [N,2]
//   d_in[1]: output    float  [N,5,5]
//   d_in[2]: target    float  [N,5]
// Output: float [N,5]
//
// Persistent kernel, 1 CTA per SM, DEEP (6-stage) TMA pipeline:
//   - prologue issues tiles 0..S-2 (stage S-1 left free)
//   - iteration k: wait mbar[k%S] -> compute (results overwrite the stage's
//     s_tgt region in place) -> commit bulk store k -> wait_group 1
//     (store k-1 complete, freeing stage (k-1)%S) -> issue tile k+S-1 there.
//   - steady state keeps 4-5 x 32KB loads in flight per SM: continuous DRAM
//     demand with zero wave transitions.

#define YI 20.0f
#define BPB 256           // boxes per tile == threads per block
#define A 5               // anchors
#define S_STAGES 6

#define OUT_BYTES (BPB * 25 * 4)   // 25600
#define TGT_BYTES (BPB * 5 * 4)    //  5120 (doubles as result buffer)
#define CEL_BYTES (BPB * 2 * 4)    //  2048
#define STAGE_BYTES (OUT_BYTES + TGT_BYTES + CEL_BYTES)   // 32768
#define SMEM_TOTAL (S_STAGES * STAGE_BYTES)               // 196608

extern __shared__ char dsm[];

__device__ __forceinline__ void mbar_wait(uint32_t mbar_a, uint32_t parity) {
    uint32_t done;
    asm volatile(
        "{\n\t"
        ".reg .pred p;\n\t"
        "mbarrier.try_wait.parity.acquire.cta.shared::cta.b64 p, [%1], %2;\n\t"
        "selp.b32 %0, 1, 0, p;\n\t"
        "}"
        : "=r"(done) : "r"(mbar_a), "r"(parity) : "memory");
    if (!done) {
        asm volatile(
            "{\n\t"
            ".reg .pred P1;\n\t"
            "WAIT_LOOP_%=:\n\t"
            "mbarrier.try_wait.parity.acquire.cta.shared::cta.b64 P1, [%0], %1, 0x989680;\n\t"
            "@P1 bra.uni WAIT_DONE_%=;\n\t"
            "bra.uni WAIT_LOOP_%=;\n\t"
            "WAIT_DONE_%=:\n\t"
            "}"
            :: "r"(mbar_a), "r"(parity) : "memory");
    }
}

__global__ __launch_bounds__(BPB, 1) void iou_kernel(
    const int* __restrict__ cell_nos,
    const float* __restrict__ output,
    const float* __restrict__ target,
    float* __restrict__ res,
    int n)
{
    __shared__ alignas(8) unsigned long long mbar[S_STAGES];

    const int tid = threadIdx.x;
    const int G   = gridDim.x;
    const int bid = blockIdx.x;
    const int ntiles = n / BPB;

    const uint32_t dsm_a   = (uint32_t)__cvta_generic_to_shared(dsm);
    const uint32_t mbar0_a = (uint32_t)__cvta_generic_to_shared(&mbar[0]);

    if (tid == 0) {
        #pragma unroll
        for (int s = 0; s < S_STAGES; s++) {
            asm volatile("mbarrier.init.shared::cta.b64 [%0], %1;"
                         :: "r"(mbar0_a + s * 8), "r"(1) : "memory");
        }
        asm volatile("fence.proxy.async.shared::cta;" ::: "memory");
    }
    __syncthreads();

    // Tiles owned by this CTA: bid, bid+G, bid+2G, ...
    const int my_nt = (ntiles > bid) ? ((ntiles - 1 - bid) / G + 1) : 0;

    // t0-only: issue the three bulk loads for owned-tile k into stage s.
    auto issue = [&](int k, int s) {
        const size_t tbase = ((size_t)bid + (size_t)k * G) * BPB;
        const uint32_t mb = mbar0_a + (uint32_t)s * 8;
        const uint32_t sb = dsm_a + (uint32_t)s * STAGE_BYTES;
        asm volatile("mbarrier.arrive.expect_tx.shared::cta.b64 _, [%0], %1;"
                     :: "r"(mb), "r"((uint32_t)STAGE_BYTES) : "memory");
        asm volatile("cp.async.bulk.shared::cta.global.mbarrier::complete_tx::bytes "
                     "[%0], [%1], %2, [%3];"
                     :: "r"(sb), "l"(output + tbase * 25),
                        "r"((uint32_t)OUT_BYTES), "r"(mb) : "memory");
        asm volatile("cp.async.bulk.shared::cta.global.mbarrier::complete_tx::bytes "
                     "[%0], [%1], %2, [%3];"
                     :: "r"(sb + OUT_BYTES), "l"(target + tbase * 5),
                        "r"((uint32_t)TGT_BYTES), "r"(mb) : "memory");
        asm volatile("cp.async.bulk.shared::cta.global.mbarrier::complete_tx::bytes "
                     "[%0], [%1], %2, [%3];"
                     :: "r"(sb + OUT_BYTES + TGT_BYTES), "l"(cell_nos + tbase * 2),
                        "r"((uint32_t)CEL_BYTES), "r"(mb) : "memory");
    };

    // Prologue: fill stages 0..S-2 (stage S-1 stays free for iteration 0's issue).
    if (tid == 0) {
        const int npro = (my_nt < S_STAGES - 1) ? my_nt : (S_STAGES - 1);
        for (int k = 0; k < npro; k++) issue(k, k);
    }

    int s = 0, epoch = 0;   // stage = k % S, parity = (k / S) & 1
    for (int k = 0; k < my_nt; k++) {
        const uint32_t mb = mbar0_a + (uint32_t)s * 8;
        char* sb = dsm + (size_t)s * STAGE_BYTES;
        float* s_out  = reinterpret_cast<float*>(sb);
        float* s_tgt  = reinterpret_cast<float*>(sb + OUT_BYTES);
        int*   s_cell = reinterpret_cast<int*>(sb + OUT_BYTES + TGT_BYTES);

        // Wait for tile k's data in stage s.
        mbar_wait(mb, (uint32_t)(epoch & 1));

        // ---- compute tile k; results overwrite s_tgt in place ----
        {
            const float ci = (float)s_cell[2 * tid]     * YI + YI * 0.5f;
            const float cj = (float)s_cell[2 * tid + 1] * YI + YI * 0.5f;

            const float* t = &s_tgt[5 * tid];
            const float g_h = t[3] * YI, g_w = t[4] * YI;
            const float gxc = ci + t[1] * YI;
            const float gyc = cj + t[2] * YI;
            const float gx1 = gyc - g_w * 0.5f;
            const float gy1 = gxc - g_h * 0.5f;
            const float gx2 = gyc + g_w * 0.5f;
            const float gy2 = gxc + g_h * 0.5f;
            const float area_g = (gx2 - gx1) * (gy2 - gy1);

            float r[A];
            #pragma unroll
            for (int a = 0; a < A; a++) {
                const float* o = &s_out[25 * tid + 5 * a];
                const float p_h = o[3] * YI, p_w = o[4] * YI;
                const float pxc = ci + o[1] * YI;
                const float pyc = cj + o[2] * YI;
                const float px1 = pyc - p_w * 0.5f;
                const float py1 = pxc - p_h * 0.5f;
                const float px2 = pyc + p_w * 0.5f;
                const float py2 = pxc + p_h * 0.5f;
                const float area_p = (px2 - px1) * (py2 - py1);

                const float lx = fmaxf(px1, gx1);
                const float ly = fmaxf(py1, gy1);
                const float rx = fminf(px2, gx2);
                const float ry = fminf(py2, gy2);
                const float iw = fmaxf(rx - lx, 0.0f);
                const float ih = fmaxf(ry - ly, 0.0f);
                const float inter = iw * ih;
                const float uni = area_p + area_g - inter;
                r[a] = __fdividef(inter, uni);
            }
            // Thread tid overwrites exactly [5*tid, 5*tid+5) which only it
            // read above -> no cross-thread hazard.
            #pragma unroll
            for (int a = 0; a < A; a++) s_tgt[5 * tid + a] = r[a];
        }
        __syncthreads();   // results complete; stage s inputs fully consumed

        if (tid == 0) {
            // Drain tile k's results (bulk_group store, in commit order k).
            const size_t tbase = ((size_t)bid + (size_t)k * G) * BPB;
            const uint32_t st_a = dsm_a + (uint32_t)s * STAGE_BYTES + OUT_BYTES;
            asm volatile("fence.proxy.async.shared::cta;" ::: "memory");
            asm volatile("cp.async.bulk.global.shared::cta.bulk_group [%0], [%1], %2;"
                         :: "l"(res + tbase * 5), "r"(st_a),
                            "r"((uint32_t)TGT_BYTES) : "memory");
            asm volatile("cp.async.bulk.commit_group;" ::: "memory");
            // Store k-1 must be complete before reloading its stage: with
            // stores k and k-1 the only possibly-outstanding groups,
            // wait_group 1 guarantees k-1 is done.
            asm volatile("cp.async.bulk.wait_group 1;" ::: "memory");
            // Issue tile k+S-1 into stage (k+S-1)%S == (k-1+S)%S (now free).
            if (k + S_STAGES - 1 < my_nt) {
                int sfree = s - 1;
                if (sfree < 0) sfree += S_STAGES;
                issue(k + S_STAGES - 1, sfree);
            }
        }

        if (++s == S_STAGES) { s = 0; epoch ^= 1; }
    }

    // Ensure all bulk stores complete before exit.
    if (tid == 0) {
        asm volatile("cp.async.bulk.wait_group 0;" ::: "memory");
    }

    // Tail boxes (n % BPB != 0): direct scalar path (never taken at bench
    // shape N=4,000,000 = 15625*256). Handled by the last CTA.
    const int rem_base = ntiles * BPB;
    if (bid == G - 1 && rem_base + tid < n) {
        const int box = rem_base + tid;
        const float ci = (float)cell_nos[2 * box]     * YI + YI * 0.5f;
        const float cj = (float)cell_nos[2 * box + 1] * YI + YI * 0.5f;
        const float* t = target + (size_t)box * 5;
        const float g_h = t[3] * YI, g_w = t[4] * YI;
        const float gxc = ci + t[1] * YI;
        const float gyc = cj + t[2] * YI;
        const float gx1 = gyc - g_w * 0.5f;
        const float gy1 = gxc - g_h * 0.5f;
        const float gx2 = gyc + g_w * 0.5f;
        const float gy2 = gxc + g_h * 0.5f;
        const float area_g = (gx2 - gx1) * (gy2 - gy1);
        #pragma unroll
        for (int a = 0; a < A; a++) {
            const float* o = output + (size_t)box * 25 + 5 * a;
            const float p_h = o[3] * YI, p_w = o[4] * YI;
            const float pxc = ci + o[1] * YI;
            const float pyc = cj + o[2] * YI;
            const float px1 = pyc - p_w * 0.5f;
            const float py1 = pxc - p_h * 0.5f;
            const float px2 = pyc + p_w * 0.5f;
            const float py2 = pxc + p_h * 0.5f;
            const float area_p = (px2 - px1) * (py2 - py1);
            const float lx = fmaxf(px1, gx1);
            const float ly = fmaxf(py1, gy1);
            const float rx = fminf(px2, gx2);
            const float ry = fminf(py2, gy2);
            const float iw = fmaxf(rx - lx, 0.0f);
            const float ih = fmaxf(ry - ly, 0.0f);
            const float inter = iw * ih;
            res[(size_t)box * 5 + a] = __fdividef(inter, area_p + area_g - inter);
        }
    }
}

extern "C" void kernel_launch(void* const* d_in, const int* in_sizes, int n_in,
                              void* d_out, int out_size) {
    const int*   cell_nos = (const int*)d_in[0];
    const float* output   = (const float*)d_in[1];
    const float* target   = (const float*)d_in[2];
    float*       res      = (float*)d_out;

    const int n = in_sizes[0] / 2;  // cell_nos is [N,2]
    const int ntiles = n / BPB;

    // Identical API sequence on every call (no static guards — harness rule).
    // Both calls are capture-safe: non-stream, non-allocating.
    int nsm = 0;
    if (cudaDeviceGetAttribute(&nsm, cudaDevAttrMultiProcessorCount, 0)
            != cudaSuccess || nsm <= 0)
        nsm = 148;  // conservative fallback (B300 die)
    cudaFuncSetAttribute(iou_kernel,
                         cudaFuncAttributeMaxDynamicSharedMemorySize,
                         SMEM_TOTAL);

    // 1 CTA per SM: no persistent CTA ever queues behind another.
    int grid = nsm;
    if (grid > ntiles) grid = (ntiles > 0) ? ntiles : 1;

    iou_kernel<<<grid, BPB, SMEM_TOTAL>>>(cell_nos, output, target, res, n);
}